// round 6
// baseline (speedup 1.0000x reference)
#include <cuda_runtime.h>
#include <cstddef>

#define LCH   4096
#define BATCH 4096
#define SEG   16
#define NTHR  256           // one block per row; thread t owns positions [16t,16t+16)

struct Pots { float pd, po, pA0, pA1, pB0, pB1; };

__device__ __forceinline__ Pots make_pots(const float* jp, const float* bp) {
    Pots P;
    float j = jp[0], b0 = bp[0], b1 = bp[1];
    P.pd  = expf( 0.25f * j);
    P.po  = expf(-0.25f * j);
    P.pA0 = expf(-0.5f * b0);  P.pA1 = expf(0.5f * b0);
    P.pB0 = expf(-0.5f * b1);  P.pB1 = expf(0.5f * b1);
    return P;
}

// (max,*) 2x2 matrix product: C = A x B.  layout x=m00 y=m01 z=m10 w=m11
__device__ __forceinline__ float4 mm(float4 A, float4 B) {
    return make_float4(
        fmaxf(A.x * B.x, A.y * B.z), fmaxf(A.x * B.y, A.y * B.w),
        fmaxf(A.z * B.x, A.w * B.z), fmaxf(A.z * B.y, A.w * B.w));
}

__device__ __forceinline__ float4 shflup4(float4 v, int d) {
    v.x = __shfl_up_sync(0xffffffffu, v.x, d);
    v.y = __shfl_up_sync(0xffffffffu, v.y, d);
    v.z = __shfl_up_sync(0xffffffffu, v.z, d);
    v.w = __shfl_up_sync(0xffffffffu, v.w, d);
    return v;
}
__device__ __forceinline__ float4 shfldn4(float4 v, int d) {
    v.x = __shfl_down_sync(0xffffffffu, v.x, d);
    v.y = __shfl_down_sync(0xffffffffu, v.y, d);
    v.z = __shfl_down_sync(0xffffffffu, v.z, d);
    v.w = __shfl_down_sync(0xffffffffu, v.w, d);
    return v;
}

// ---------------------------------------------------------------------------
// One block per row, SEG=16. Segment matrices -> 8-warp (max,*) matrix scan
// -> forward store pass -> backward RMW pass -> coalesced store.
// ---------------------------------------------------------------------------
__global__ void __launch_bounds__(NTHR, 2)
fused(const float* __restrict__ jp, const float* __restrict__ bp,
      const int* __restrict__ obs, float* __restrict__ out)
{
    const int t = threadIdx.x, b = blockIdx.x;
    const int lane = t & 31, warp = t >> 5;

    __shared__ unsigned char smNib[1024];
    __shared__ float4 lutP[16], lutQ[16];
    __shared__ float4 wTotP[8], wTotQ[8];
    __shared__ float  smo[2 * LCH];         // 32 KB output stage
    float4* sm4 = reinterpret_cast<float4*>(smo);

    const Pots pt = make_pots(jp, bp);

    // ---- obs -> nibbles (coalesced int4 loads, 4 per thread) ----
    const int4* row4 = reinterpret_cast<const int4*>(obs + (size_t)b * LCH);
#pragma unroll
    for (int q = 0; q < 4; q++) {
        int  eq = q * NTHR + t;
        int4 v  = row4[eq];
        unsigned nib = (v.x & 1) | ((v.y & 1) << 1) | ((v.z & 1) << 2) | ((v.w & 1) << 3);
        smNib[eq] = (unsigned char)nib;
    }

    // ---- 4-bit LUTs of 4-step transfer matrices ----
    if (t < 16) {
        float p00 = 1.f, p01 = 0.f, p10 = 0.f, p11 = 1.f;
        float q00 = 1.f, q01 = 0.f, q10 = 0.f, q11 = 1.f;
#pragma unroll
        for (int i = 0; i < 4; i++) {
            int   o  = (t >> i) & 1;
            float f0 = o ? pt.pB0 : pt.pA0;
            float f1 = o ? pt.pB1 : pt.pA1;
            float x0 = f0 * p00, x1 = f1 * p10, y0 = f0 * p01, y1 = f1 * p11;
            p00 = fmaxf(x0 * pt.pd, x1 * pt.po); p10 = fmaxf(x0 * pt.po, x1 * pt.pd);
            p01 = fmaxf(y0 * pt.pd, y1 * pt.po); p11 = fmaxf(y0 * pt.po, y1 * pt.pd);
            float a = f0 * fmaxf(q00 * pt.pd, q01 * pt.po);
            float c = f1 * fmaxf(q00 * pt.po, q01 * pt.pd);
            float d = f0 * fmaxf(q10 * pt.pd, q11 * pt.po);
            float e = f1 * fmaxf(q10 * pt.po, q11 * pt.pd);
            q00 = a; q01 = c; q10 = d; q11 = e;
        }
        lutP[t] = make_float4(p00, p01, p10, p11);
        lutQ[t] = make_float4(q00, q01, q10, q11);
    }
    __syncthreads();

    // ---- 16-bit obs mask for segment t (4 nibbles) ----
    unsigned u  = *reinterpret_cast<const unsigned*>(smNib + 4 * t);
    unsigned lo = u | (u >> 4);
    const unsigned bits = (lo & 0xFFu) | ((lo >> 8) & 0xFF00u);

    // ---- segment transfer matrices via LUT chain (4 nibbles) ----
    float4 P = lutP[bits & 15];
    float4 Q = lutQ[bits & 15];
#pragma unroll
    for (int c = 1; c < 4; c++) {
        unsigned m = (bits >> (4 * c)) & 15u;
        P = mm(lutP[m], P);
        Q = mm(Q, lutQ[m]);
    }

    // ---- block scan: forward prefix of P, backward suffix of Q ----
    float4 sp = P;
#pragma unroll
    for (int d = 1; d < 32; d <<= 1) {
        float4 o = shflup4(sp, d);
        if (lane >= d) sp = mm(sp, o);
    }
    if (lane == 31) wTotP[warp] = sp;

    float4 sq = Q;
#pragma unroll
    for (int d = 1; d < 32; d <<= 1) {
        float4 o = shfldn4(sq, d);
        if (lane + d < 32) sq = mm(sq, o);
    }
    if (lane == 0) wTotQ[warp] = sq;
    __syncthreads();

    float4 prefP = make_float4(1.f, 0.f, 0.f, 1.f);
#pragma unroll
    for (int k = 6; k >= 0; k--)
        if (warp > k) prefP = mm(prefP, wTotP[k]);

    float4 sufQ = make_float4(1.f, 0.f, 0.f, 1.f);
#pragma unroll
    for (int k = 1; k < 8; k++)
        if (warp < k) sufQ = mm(sufQ, wTotQ[k]);

    float4 exP = shflup4(sp, 1);
    if (lane == 0) exP = make_float4(1.f, 0.f, 0.f, 1.f);
    exP = mm(exP, prefP);
    float f0 = fmaxf(exP.x, exP.y), f1 = fmaxf(exP.z, exP.w);  // fwd msg into seg start

    float4 exQ = shfldn4(sq, 1);
    if (lane == 31) exQ = make_float4(1.f, 0.f, 0.f, 1.f);
    exQ = mm(exQ, sufQ);
    float g0 = fmaxf(exQ.x, exQ.y), g1 = fmaxf(exQ.z, exQ.w);  // bwd msg into seg end

    // ---- forward pass: x = phi*f into swizzled tile (own region only) ----
    const int xr = (t >> 1) & 3;
#pragma unroll
    for (int gg = 0; gg < 4; gg++) {
        float v0[4], v1[4];
#pragma unroll
        for (int uu = 0; uu < 4; uu++) {
            int   i  = gg * 4 + uu;
            int   o  = (bits >> i) & 1;
            float p0 = o ? pt.pB0 : pt.pA0;
            float p1 = o ? pt.pB1 : pt.pA1;
            float x0 = p0 * f0, x1 = p1 * f1;
            v0[uu] = x0;  v1[uu] = x1;
            f0 = fmaxf(x0 * pt.pd, x1 * pt.po);
            f1 = fmaxf(x0 * pt.po, x1 * pt.pd);
        }
        sm4[(t * 4 + gg) ^ xr]        = make_float4(v0[0], v0[1], v0[2], v0[3]);
        sm4[(1024 + t * 4 + gg) ^ xr] = make_float4(v1[0], v1[1], v1[2], v1[3]);
    }

    // ---- backward RMW pass: multiply own tile entries by backward msg ----
    float bk0 = g0, bk1 = g1;
#pragma unroll
    for (int gg = 3; gg >= 0; gg--) {
        float a0[4], a1[4];
        *reinterpret_cast<float4*>(a0) = sm4[(t * 4 + gg) ^ xr];
        *reinterpret_cast<float4*>(a1) = sm4[(1024 + t * 4 + gg) ^ xr];
        float r0[4], r1[4];
#pragma unroll
        for (int uu = 3; uu >= 0; uu--) {
            int   i  = gg * 4 + uu;
            r0[uu] = a0[uu] * bk0;
            r1[uu] = a1[uu] * bk1;
            int   o  = (bits >> i) & 1;
            float p0 = o ? pt.pB0 : pt.pA0;
            float p1 = o ? pt.pB1 : pt.pA1;
            float y0 = p0 * bk0, y1 = p1 * bk1;
            bk0 = fmaxf(y0 * pt.pd, y1 * pt.po);
            bk1 = fmaxf(y0 * pt.po, y1 * pt.pd);
        }
        sm4[(t * 4 + gg) ^ xr]        = *reinterpret_cast<float4*>(r0);
        sm4[(1024 + t * 4 + gg) ^ xr] = *reinterpret_cast<float4*>(r1);
    }
    __syncthreads();

    // ---- cooperative fully-coalesced store: out[b][k][t] ----
    float4* out4 = reinterpret_cast<float4*>(out) + (size_t)b * 2048;
#pragma unroll
    for (int r = 0; r < 8; r++) {
        int w4 = r * NTHR + t;
        int x  = (w4 >> 3) & 3;
        out4[w4] = sm4[w4 ^ x];
    }
}

// ---------------------------------------------------------------------------
extern "C" void kernel_launch(void* const* d_in, const int* in_sizes, int n_in,
                              void* d_out, int out_size)
{
    const float* jp  = nullptr;
    const float* bp  = nullptr;
    const int*   obs = nullptr;
    for (int i = 0; i < n_in; i++) {
        if (in_sizes[i] == 1)      jp  = (const float*)d_in[i];
        else if (in_sizes[i] == 2) bp  = (const float*)d_in[i];
        else                       obs = (const int*)d_in[i];
    }
    float* out = (float*)d_out;

    fused<<<BATCH, NTHR>>>(jp, bp, obs, out);
}

// round 7
// speedup vs baseline: 1.0445x; 1.0445x over previous
#include <cuda_runtime.h>
#include <cstddef>

#define LCH   4096
#define BATCH 4096
#define NTHR  256
#define NSEG  128          // segments of 32; fwd threads 0-127, bwd threads 128-255

// dynamic smem layout (bytes)
#define OFF_X    0          // 32 KB  x = phi*f tile
#define OFF_B    32768      // 32 KB  backward-message tile
#define OFF_NIB  65536      // 1 KB   obs nibbles
#define OFF_LUTP 66560      // 256 B
#define OFF_LUTQ 66816      // 256 B
#define OFF_WTOT 67072      // 128 B  warp scan totals (0-3 P, 4-7 Q)
#define SMEM_TOTAL 67328

struct Pots { float pd, po, pA0, pA1, pB0, pB1; };

__device__ __forceinline__ Pots make_pots(const float* jp, const float* bp) {
    Pots P;
    float j = jp[0], b0 = bp[0], b1 = bp[1];
    P.pd  = expf( 0.25f * j);
    P.po  = expf(-0.25f * j);
    P.pA0 = expf(-0.5f * b0);  P.pA1 = expf(0.5f * b0);
    P.pB0 = expf(-0.5f * b1);  P.pB1 = expf(0.5f * b1);
    return P;
}

// (max,*) 2x2 matrix product: C = A x B.  layout x=m00 y=m01 z=m10 w=m11
__device__ __forceinline__ float4 mm(float4 A, float4 B) {
    return make_float4(
        fmaxf(A.x * B.x, A.y * B.z), fmaxf(A.x * B.y, A.y * B.w),
        fmaxf(A.z * B.x, A.w * B.z), fmaxf(A.z * B.y, A.w * B.w));
}

__device__ __forceinline__ float4 shflup4(float4 v, int d) {
    v.x = __shfl_up_sync(0xffffffffu, v.x, d);
    v.y = __shfl_up_sync(0xffffffffu, v.y, d);
    v.z = __shfl_up_sync(0xffffffffu, v.z, d);
    v.w = __shfl_up_sync(0xffffffffu, v.w, d);
    return v;
}
__device__ __forceinline__ float4 shfldn4(float4 v, int d) {
    v.x = __shfl_down_sync(0xffffffffu, v.x, d);
    v.y = __shfl_down_sync(0xffffffffu, v.y, d);
    v.z = __shfl_down_sync(0xffffffffu, v.z, d);
    v.w = __shfl_down_sync(0xffffffffu, v.w, d);
    return v;
}

// ---------------------------------------------------------------------------
// One block per row. Warps 0-3: forward direction; warps 4-7: backward
// direction, fully concurrent. Belief multiply fused into coalesced store.
// ---------------------------------------------------------------------------
__global__ void __launch_bounds__(NTHR, 3)
fused(const float* __restrict__ jp, const float* __restrict__ bp,
      const int* __restrict__ obs, float* __restrict__ out)
{
    extern __shared__ char dyn[];
    float4*        X4    = reinterpret_cast<float4*>(dyn + OFF_X);
    float4*        B4    = reinterpret_cast<float4*>(dyn + OFF_B);
    unsigned char* smNib = reinterpret_cast<unsigned char*>(dyn + OFF_NIB);
    float4*        lutP  = reinterpret_cast<float4*>(dyn + OFF_LUTP);
    float4*        lutQ  = reinterpret_cast<float4*>(dyn + OFF_LUTQ);
    float4*        wTot  = reinterpret_cast<float4*>(dyn + OFF_WTOT);

    const int t = threadIdx.x, b = blockIdx.x;
    const int lane = t & 31, warp = t >> 5;
    const Pots pt = make_pots(jp, bp);

    // ---- obs -> nibbles (coalesced int4 loads, 4 per thread) ----
    const int4* row4 = reinterpret_cast<const int4*>(obs + (size_t)b * LCH);
#pragma unroll
    for (int q = 0; q < 4; q++) {
        int  eq = q * NTHR + t;
        int4 v  = row4[eq];
        smNib[eq] = (unsigned char)((v.x & 1) | ((v.y & 1) << 1) |
                                    ((v.z & 1) << 2) | ((v.w & 1) << 3));
    }

    // ---- 4-bit LUTs of 4-step transfer matrices ----
    if (t < 16) {
        float p00 = 1.f, p01 = 0.f, p10 = 0.f, p11 = 1.f;
        float q00 = 1.f, q01 = 0.f, q10 = 0.f, q11 = 1.f;
#pragma unroll
        for (int i = 0; i < 4; i++) {
            int   o  = (t >> i) & 1;
            float f0 = o ? pt.pB0 : pt.pA0;
            float f1 = o ? pt.pB1 : pt.pA1;
            float x0 = f0 * p00, x1 = f1 * p10, y0 = f0 * p01, y1 = f1 * p11;
            p00 = fmaxf(x0 * pt.pd, x1 * pt.po); p10 = fmaxf(x0 * pt.po, x1 * pt.pd);
            p01 = fmaxf(y0 * pt.pd, y1 * pt.po); p11 = fmaxf(y0 * pt.po, y1 * pt.pd);
            float a = f0 * fmaxf(q00 * pt.pd, q01 * pt.po);
            float c = f1 * fmaxf(q00 * pt.po, q01 * pt.pd);
            float d = f0 * fmaxf(q10 * pt.pd, q11 * pt.po);
            float e = f1 * fmaxf(q10 * pt.po, q11 * pt.pd);
            q00 = a; q01 = c; q10 = d; q11 = e;
        }
        lutP[t] = make_float4(p00, p01, p10, p11);
        lutQ[t] = make_float4(q00, q01, q10, q11);
    }
    __syncthreads();

    // ---- 32-bit obs mask for segment s ----
    const int s = t & 127;
    uint2 nb = reinterpret_cast<const uint2*>(smNib)[s];
    unsigned lo   = nb.x | (nb.x >> 4);
    unsigned lo16 = (lo & 0xFFu) | ((lo >> 8) & 0xFF00u);
    unsigned hi   = nb.y | (nb.y >> 4);
    unsigned hi16 = (hi & 0xFFu) | ((hi >> 8) & 0xFF00u);
    const unsigned bits = lo16 | (hi16 << 16);

    const bool isFwd = (t < 128);

    // ---- segment transfer matrix + warp scan (direction-split) ----
    float4 sv;
    if (isFwd) {
        sv = lutP[bits & 15];
#pragma unroll
        for (int c = 1; c < 8; c++)
            sv = mm(lutP[(bits >> (4 * c)) & 15u], sv);
#pragma unroll
        for (int d = 1; d < 32; d <<= 1) {
            float4 o = shflup4(sv, d);
            if (lane >= d) sv = mm(sv, o);
        }
        if (lane == 31) wTot[warp] = sv;
    } else {
        sv = lutQ[bits & 15];
#pragma unroll
        for (int c = 1; c < 8; c++)
            sv = mm(sv, lutQ[(bits >> (4 * c)) & 15u]);
#pragma unroll
        for (int d = 1; d < 32; d <<= 1) {
            float4 o = shfldn4(sv, d);
            if (lane + d < 32) sv = mm(sv, o);
        }
        if (lane == 0) wTot[warp] = sv;
    }
    __syncthreads();

    const int xr = s & 7;
    if (isFwd) {
        // cross-warp exclusive prefix
        float4 pref = make_float4(1.f, 0.f, 0.f, 1.f);
#pragma unroll
        for (int k = 2; k >= 0; k--)
            if (warp > k) pref = mm(pref, wTot[k]);
        float4 ex = shflup4(sv, 1);
        if (lane == 0) ex = make_float4(1.f, 0.f, 0.f, 1.f);
        ex = mm(ex, pref);
        float f0 = fmaxf(ex.x, ex.y), f1 = fmaxf(ex.z, ex.w);  // fwd msg at seg start

        // forward sweep: x = phi*f into X tile
#pragma unroll
        for (int gg = 0; gg < 8; gg++) {
            float v0[4], v1[4];
#pragma unroll
            for (int u = 0; u < 4; u++) {
                int   i  = gg * 4 + u;
                int   o  = (bits >> i) & 1;
                float p0 = o ? pt.pB0 : pt.pA0;
                float p1 = o ? pt.pB1 : pt.pA1;
                float x0 = p0 * f0, x1 = p1 * f1;
                v0[u] = x0;  v1[u] = x1;
                f0 = fmaxf(x0 * pt.pd, x1 * pt.po);
                f1 = fmaxf(x0 * pt.po, x1 * pt.pd);
            }
            X4[(s * 8 + gg) ^ xr]        = make_float4(v0[0], v0[1], v0[2], v0[3]);
            X4[(1024 + s * 8 + gg) ^ xr] = make_float4(v1[0], v1[1], v1[2], v1[3]);
        }
    } else {
        // cross-warp exclusive suffix (bwd warps 4-7 -> wq 0-3)
        const int wq = warp - 4;
        float4 suf = make_float4(1.f, 0.f, 0.f, 1.f);
#pragma unroll
        for (int k = 1; k < 4; k++)
            if (wq < k) suf = mm(suf, wTot[4 + k]);
        float4 ex = shfldn4(sv, 1);
        if (lane == 31) ex = make_float4(1.f, 0.f, 0.f, 1.f);
        ex = mm(ex, suf);
        float bk0 = fmaxf(ex.x, ex.y), bk1 = fmaxf(ex.z, ex.w); // bwd msg at seg end

        // backward sweep: b_i into B tile (descending)
#pragma unroll
        for (int gg = 7; gg >= 0; gg--) {
            float w0[4], w1[4];
#pragma unroll
            for (int u = 3; u >= 0; u--) {
                int i = gg * 4 + u;
                w0[u] = bk0;  w1[u] = bk1;
                int   o  = (bits >> i) & 1;
                float p0 = o ? pt.pB0 : pt.pA0;
                float p1 = o ? pt.pB1 : pt.pA1;
                float y0 = p0 * bk0, y1 = p1 * bk1;
                bk0 = fmaxf(y0 * pt.pd, y1 * pt.po);
                bk1 = fmaxf(y0 * pt.po, y1 * pt.pd);
            }
            B4[(s * 8 + gg) ^ xr]        = make_float4(w0[0], w0[1], w0[2], w0[3]);
            B4[(1024 + s * 8 + gg) ^ xr] = make_float4(w1[0], w1[1], w1[2], w1[3]);
        }
    }
    __syncthreads();

    // ---- fused belief multiply + coalesced store: out[b][k][t] ----
    float4* out4 = reinterpret_cast<float4*>(out) + (size_t)b * 2048;
#pragma unroll
    for (int r = 0; r < 8; r++) {
        int w4 = r * NTHR + t;
        int x  = (w4 >> 3) & 7;
        float4 xv = X4[w4 ^ x];
        float4 bv = B4[w4 ^ x];
        out4[w4] = make_float4(xv.x * bv.x, xv.y * bv.y, xv.z * bv.z, xv.w * bv.w);
    }
}

// ---------------------------------------------------------------------------
extern "C" void kernel_launch(void* const* d_in, const int* in_sizes, int n_in,
                              void* d_out, int out_size)
{
    const float* jp  = nullptr;
    const float* bp  = nullptr;
    const int*   obs = nullptr;
    for (int i = 0; i < n_in; i++) {
        if (in_sizes[i] == 1)      jp  = (const float*)d_in[i];
        else if (in_sizes[i] == 2) bp  = (const float*)d_in[i];
        else                       obs = (const int*)d_in[i];
    }
    float* out = (float*)d_out;

    cudaFuncSetAttribute(fused, cudaFuncAttributeMaxDynamicSharedMemorySize, SMEM_TOTAL);
    fused<<<BATCH, NTHR, SMEM_TOTAL>>>(jp, bp, obs, out);
}

// round 8
// speedup vs baseline: 1.0866x; 1.0403x over previous
#include <cuda_runtime.h>
#include <cstddef>

#define LCH   4096
#define BATCH 4096
#define SEG   32
#define NSEG  128

struct Pots { float pd, po, pA0, pA1, pB0, pB1; };

__device__ __forceinline__ Pots make_pots(const float* jp, const float* bp) {
    Pots P;
    float j = jp[0], b0 = bp[0], b1 = bp[1];
    P.pd  = expf( 0.25f * j);
    P.po  = expf(-0.25f * j);
    P.pA0 = expf(-0.5f * b0);  P.pA1 = expf(0.5f * b0);
    P.pB0 = expf(-0.5f * b1);  P.pB1 = expf(0.5f * b1);
    return P;
}

// (max,*) 2x2 matrix product: C = A x B.  layout x=m00 y=m01 z=m10 w=m11
__device__ __forceinline__ float4 mm(float4 A, float4 B) {
    return make_float4(
        fmaxf(A.x * B.x, A.y * B.z), fmaxf(A.x * B.y, A.y * B.w),
        fmaxf(A.z * B.x, A.w * B.z), fmaxf(A.z * B.y, A.w * B.w));
}

__device__ __forceinline__ float4 shflup4(float4 v, int d) {
    v.x = __shfl_up_sync(0xffffffffu, v.x, d);
    v.y = __shfl_up_sync(0xffffffffu, v.y, d);
    v.z = __shfl_up_sync(0xffffffffu, v.z, d);
    v.w = __shfl_up_sync(0xffffffffu, v.w, d);
    return v;
}
__device__ __forceinline__ float4 shfldn4(float4 v, int d) {
    v.x = __shfl_down_sync(0xffffffffu, v.x, d);
    v.y = __shfl_down_sync(0xffffffffu, v.y, d);
    v.z = __shfl_down_sync(0xffffffffu, v.z, d);
    v.w = __shfl_down_sync(0xffffffffu, v.w, d);
    return v;
}

// ---------------------------------------------------------------------------
// One block per row (R3 structure). Segment matrices -> block (max,*) scan
// -> backward sweep into registers -> forward sweep writes FINAL beliefs to
// the tile (single STS pass) -> single LDS pass + coalesced store.
// ---------------------------------------------------------------------------
__global__ void __launch_bounds__(128, 3)
fused(const float* __restrict__ jp, const float* __restrict__ bp,
      const int* __restrict__ obs, float* __restrict__ out)
{
    const int t = threadIdx.x, b = blockIdx.x;
    const int lane = t & 31, warp = t >> 5;

    __shared__ unsigned char smNib[1024];
    __shared__ float4 lutP[16], lutQ[16];
    __shared__ float4 wTotP[4], wTotQ[4];
    __shared__ float  smo[2 * LCH];         // 32 KB output stage
    float4* sm4 = reinterpret_cast<float4*>(smo);

    const Pots pt = make_pots(jp, bp);

    // ---- obs -> nibbles (coalesced int4 loads) ----
    const int4* row4 = reinterpret_cast<const int4*>(obs + (size_t)b * LCH);
#pragma unroll
    for (int q = 0; q < 8; q++) {
        int  eq = q * 128 + t;
        int4 v  = row4[eq];
        smNib[eq] = (unsigned char)((v.x & 1) | ((v.y & 1) << 1) |
                                    ((v.z & 1) << 2) | ((v.w & 1) << 3));
    }

    // ---- 4-bit LUTs of 4-step transfer matrices ----
    if (t < 16) {
        float p00 = 1.f, p01 = 0.f, p10 = 0.f, p11 = 1.f;
        float q00 = 1.f, q01 = 0.f, q10 = 0.f, q11 = 1.f;
#pragma unroll
        for (int i = 0; i < 4; i++) {
            int   o  = (t >> i) & 1;
            float f0 = o ? pt.pB0 : pt.pA0;
            float f1 = o ? pt.pB1 : pt.pA1;
            float x0 = f0 * p00, x1 = f1 * p10, y0 = f0 * p01, y1 = f1 * p11;
            p00 = fmaxf(x0 * pt.pd, x1 * pt.po); p10 = fmaxf(x0 * pt.po, x1 * pt.pd);
            p01 = fmaxf(y0 * pt.pd, y1 * pt.po); p11 = fmaxf(y0 * pt.po, y1 * pt.pd);
            float a = f0 * fmaxf(q00 * pt.pd, q01 * pt.po);
            float c = f1 * fmaxf(q00 * pt.po, q01 * pt.pd);
            float d = f0 * fmaxf(q10 * pt.pd, q11 * pt.po);
            float e = f1 * fmaxf(q10 * pt.po, q11 * pt.pd);
            q00 = a; q01 = c; q10 = d; q11 = e;
        }
        lutP[t] = make_float4(p00, p01, p10, p11);
        lutQ[t] = make_float4(q00, q01, q10, q11);
    }
    __syncthreads();

    // ---- assemble 32-bit mask for segment t ----
    uint2 nb = reinterpret_cast<const uint2*>(smNib)[t];
    unsigned lo   = nb.x | (nb.x >> 4);
    unsigned lo16 = (lo & 0xFFu) | ((lo >> 8) & 0xFF00u);
    unsigned hi   = nb.y | (nb.y >> 4);
    unsigned hi16 = (hi & 0xFFu) | ((hi >> 8) & 0xFF00u);
    const unsigned bits = lo16 | (hi16 << 16);

    // ---- segment transfer matrices via LUT chains ----
    float4 P = lutP[bits & 15];
    float4 Q = lutQ[bits & 15];
#pragma unroll
    for (int c = 1; c < 8; c++) {
        unsigned m = (bits >> (4 * c)) & 15u;
        P = mm(lutP[m], P);
        Q = mm(Q, lutQ[m]);
    }

    // ---- block scan: forward prefix of P, backward suffix of Q ----
    float4 sp = P;
#pragma unroll
    for (int d = 1; d < 32; d <<= 1) {
        float4 o = shflup4(sp, d);
        if (lane >= d) sp = mm(sp, o);
    }
    if (lane == 31) wTotP[warp] = sp;

    float4 sq = Q;
#pragma unroll
    for (int d = 1; d < 32; d <<= 1) {
        float4 o = shfldn4(sq, d);
        if (lane + d < 32) sq = mm(sq, o);
    }
    if (lane == 0) wTotQ[warp] = sq;
    __syncthreads();

    float4 prefP = make_float4(1.f, 0.f, 0.f, 1.f);
#pragma unroll
    for (int k = 2; k >= 0; k--)
        if (warp > k) prefP = mm(prefP, wTotP[k]);

    float4 sufQ = make_float4(1.f, 0.f, 0.f, 1.f);
#pragma unroll
    for (int k = 1; k < 4; k++)
        if (warp < k) sufQ = mm(sufQ, wTotQ[k]);

    float4 exP = shflup4(sp, 1);
    if (lane == 0) exP = make_float4(1.f, 0.f, 0.f, 1.f);
    exP = mm(exP, prefP);
    float f0 = fmaxf(exP.x, exP.y), f1 = fmaxf(exP.z, exP.w);  // fwd msg at seg start

    float4 exQ = shfldn4(sq, 1);
    if (lane == 31) exQ = make_float4(1.f, 0.f, 0.f, 1.f);
    exQ = mm(exQ, sufQ);
    float g0 = fmaxf(exQ.x, exQ.y), g1 = fmaxf(exQ.z, exQ.w);  // bwd msg at seg end

    // ---- backward sweep FIRST: keep all 32 b-values in registers ----
    float bk0[SEG], bk1[SEG];
    bk0[SEG - 1] = g0;  bk1[SEG - 1] = g1;
#pragma unroll
    for (int i = SEG - 2; i >= 0; i--) {
        int   o  = (bits >> (i + 1)) & 1;
        float p0 = o ? pt.pB0 : pt.pA0;
        float p1 = o ? pt.pB1 : pt.pA1;
        float y0 = p0 * bk0[i + 1];
        float y1 = p1 * bk1[i + 1];
        bk0[i] = fmaxf(y0 * pt.pd, y1 * pt.po);
        bk1[i] = fmaxf(y0 * pt.po, y1 * pt.pd);
    }

    // ---- forward sweep: write FINAL beliefs phi*f*b to tile (one STS pass) ----
    const int xr = t & 7;
#pragma unroll
    for (int gg = 0; gg < 8; gg++) {
        float v0[4], v1[4];
#pragma unroll
        for (int u = 0; u < 4; u++) {
            int   i  = gg * 4 + u;
            int   o  = (bits >> i) & 1;
            float p0 = o ? pt.pB0 : pt.pA0;
            float p1 = o ? pt.pB1 : pt.pA1;
            float x0 = p0 * f0, x1 = p1 * f1;
            v0[u] = x0 * bk0[i];
            v1[u] = x1 * bk1[i];
            f0 = fmaxf(x0 * pt.pd, x1 * pt.po);
            f1 = fmaxf(x0 * pt.po, x1 * pt.pd);
        }
        sm4[(t * 8 + gg) ^ xr]        = make_float4(v0[0], v0[1], v0[2], v0[3]);
        sm4[(1024 + t * 8 + gg) ^ xr] = make_float4(v1[0], v1[1], v1[2], v1[3]);
    }
    __syncthreads();

    // ---- single LDS pass + fully-coalesced store: out[b][k][t] ----
    float4* out4 = reinterpret_cast<float4*>(out) + (size_t)b * 2048;
#pragma unroll
    for (int r = 0; r < 16; r++) {
        int w4 = r * 128 + t;
        int x  = (w4 >> 3) & 7;
        out4[w4] = sm4[w4 ^ x];
    }
}

// ---------------------------------------------------------------------------
extern "C" void kernel_launch(void* const* d_in, const int* in_sizes, int n_in,
                              void* d_out, int out_size)
{
    const float* jp  = nullptr;
    const float* bp  = nullptr;
    const int*   obs = nullptr;
    for (int i = 0; i < n_in; i++) {
        if (in_sizes[i] == 1)      jp  = (const float*)d_in[i];
        else if (in_sizes[i] == 2) bp  = (const float*)d_in[i];
        else                       obs = (const int*)d_in[i];
    }
    float* out = (float*)d_out;

    fused<<<BATCH, 128>>>(jp, bp, obs, out);
}

// round 9
// speedup vs baseline: 1.2095x; 1.1131x over previous
#include <cuda_runtime.h>
#include <cstddef>

#define LCH   4096
#define BATCH 4096
#define SEG   32
#define NSEG  128

struct Pots { float pd, po, pA0, pA1, pB0, pB1; };

__device__ __forceinline__ Pots make_pots(const float* jp, const float* bp) {
    Pots P;
    float j = jp[0], b0 = bp[0], b1 = bp[1];
    P.pd  = expf( 0.25f * j);
    P.po  = expf(-0.25f * j);
    P.pA0 = expf(-0.5f * b0);  P.pA1 = expf(0.5f * b0);
    P.pB0 = expf(-0.5f * b1);  P.pB1 = expf(0.5f * b1);
    return P;
}

// (max,*) 2x2 matrix product: C = A x B.  layout x=m00 y=m01 z=m10 w=m11
__device__ __forceinline__ float4 mm(float4 A, float4 B) {
    return make_float4(
        fmaxf(A.x * B.x, A.y * B.z), fmaxf(A.x * B.y, A.y * B.w),
        fmaxf(A.z * B.x, A.w * B.z), fmaxf(A.z * B.y, A.w * B.w));
}

__device__ __forceinline__ float4 shflup4(float4 v, int d) {
    v.x = __shfl_up_sync(0xffffffffu, v.x, d);
    v.y = __shfl_up_sync(0xffffffffu, v.y, d);
    v.z = __shfl_up_sync(0xffffffffu, v.z, d);
    v.w = __shfl_up_sync(0xffffffffu, v.w, d);
    return v;
}
__device__ __forceinline__ float4 shfldn4(float4 v, int d) {
    v.x = __shfl_down_sync(0xffffffffu, v.x, d);
    v.y = __shfl_down_sync(0xffffffffu, v.y, d);
    v.z = __shfl_down_sync(0xffffffffu, v.z, d);
    v.w = __shfl_down_sync(0xffffffffu, v.w, d);
    return v;
}

// ---------------------------------------------------------------------------
// One block per row. Segment matrices -> block (max,*) scan. Backward chain
// broken into 8 independent chunks via saved Q-suffix products SS[g]; belief
// computed in a single fused sweep -> one STS pass -> coalesced store.
// ---------------------------------------------------------------------------
__global__ void __launch_bounds__(128, 4)
fused(const float* __restrict__ jp, const float* __restrict__ bp,
      const int* __restrict__ obs, float* __restrict__ out)
{
    const int t = threadIdx.x, b = blockIdx.x;
    const int lane = t & 31, warp = t >> 5;

    __shared__ unsigned char smNib[1024];
    __shared__ float4 lutP[16], lutQ[16];
    __shared__ float4 wTotP[4], wTotQ[4];
    __shared__ float  smo[2 * LCH];         // 32 KB output stage
    float4* sm4 = reinterpret_cast<float4*>(smo);

    const Pots pt = make_pots(jp, bp);

    // ---- obs -> nibbles (coalesced int4 loads) ----
    const int4* row4 = reinterpret_cast<const int4*>(obs + (size_t)b * LCH);
#pragma unroll
    for (int q = 0; q < 8; q++) {
        int  eq = q * 128 + t;
        int4 v  = row4[eq];
        smNib[eq] = (unsigned char)((v.x & 1) | ((v.y & 1) << 1) |
                                    ((v.z & 1) << 2) | ((v.w & 1) << 3));
    }

    // ---- 4-bit LUTs of 4-step transfer matrices ----
    if (t < 16) {
        float p00 = 1.f, p01 = 0.f, p10 = 0.f, p11 = 1.f;
        float q00 = 1.f, q01 = 0.f, q10 = 0.f, q11 = 1.f;
#pragma unroll
        for (int i = 0; i < 4; i++) {
            int   o  = (t >> i) & 1;
            float f0 = o ? pt.pB0 : pt.pA0;
            float f1 = o ? pt.pB1 : pt.pA1;
            float x0 = f0 * p00, x1 = f1 * p10, y0 = f0 * p01, y1 = f1 * p11;
            p00 = fmaxf(x0 * pt.pd, x1 * pt.po); p10 = fmaxf(x0 * pt.po, x1 * pt.pd);
            p01 = fmaxf(y0 * pt.pd, y1 * pt.po); p11 = fmaxf(y0 * pt.po, y1 * pt.pd);
            float a = f0 * fmaxf(q00 * pt.pd, q01 * pt.po);
            float c = f1 * fmaxf(q00 * pt.po, q01 * pt.pd);
            float d = f0 * fmaxf(q10 * pt.pd, q11 * pt.po);
            float e = f1 * fmaxf(q10 * pt.po, q11 * pt.pd);
            q00 = a; q01 = c; q10 = d; q11 = e;
        }
        lutP[t] = make_float4(p00, p01, p10, p11);
        lutQ[t] = make_float4(q00, q01, q10, q11);
    }
    __syncthreads();

    // ---- assemble 32-bit mask for segment t ----
    uint2 nb = reinterpret_cast<const uint2*>(smNib)[t];
    unsigned lo   = nb.x | (nb.x >> 4);
    unsigned lo16 = (lo & 0xFFu) | ((lo >> 8) & 0xFF00u);
    unsigned hi   = nb.y | (nb.y >> 4);
    unsigned hi16 = (hi & 0xFFu) | ((hi >> 8) & 0xFF00u);
    const unsigned bits = lo16 | (hi16 << 16);

    // ---- P total (fwd) and Q suffix products SS[g] (bwd chain breaker) ----
    float4 P = lutP[bits & 15];
#pragma unroll
    for (int c = 1; c < 8; c++)
        P = mm(lutP[(bits >> (4 * c)) & 15u], P);

    float4 SS[8];                 // SS[g] = chunkQ_{g+1} . ... . chunkQ_7
    float4 Q = make_float4(1.f, 0.f, 0.f, 1.f);
#pragma unroll
    for (int c = 7; c >= 0; c--) {
        SS[c] = Q;
        Q = mm(lutQ[(bits >> (4 * c)) & 15u], Q);
    }
    // Q is now the full segment backward matrix (position order product)

    // ---- block scan: forward prefix of P, backward suffix of Q ----
    float4 sp = P;
#pragma unroll
    for (int d = 1; d < 32; d <<= 1) {
        float4 o = shflup4(sp, d);
        if (lane >= d) sp = mm(sp, o);
    }
    if (lane == 31) wTotP[warp] = sp;

    float4 sq = Q;
#pragma unroll
    for (int d = 1; d < 32; d <<= 1) {
        float4 o = shfldn4(sq, d);
        if (lane + d < 32) sq = mm(sq, o);
    }
    if (lane == 0) wTotQ[warp] = sq;
    __syncthreads();

    float4 prefP = make_float4(1.f, 0.f, 0.f, 1.f);
#pragma unroll
    for (int k = 2; k >= 0; k--)
        if (warp > k) prefP = mm(prefP, wTotP[k]);

    float4 sufQ = make_float4(1.f, 0.f, 0.f, 1.f);
#pragma unroll
    for (int k = 1; k < 4; k++)
        if (warp < k) sufQ = mm(sufQ, wTotQ[k]);

    float4 exP = shflup4(sp, 1);
    if (lane == 0) exP = make_float4(1.f, 0.f, 0.f, 1.f);
    exP = mm(exP, prefP);
    float f0 = fmaxf(exP.x, exP.y), f1 = fmaxf(exP.z, exP.w);  // fwd msg at seg start

    float4 exQ = shfldn4(sq, 1);
    if (lane == 31) exQ = make_float4(1.f, 0.f, 0.f, 1.f);
    exQ = mm(exQ, sufQ);
    const float g0 = fmaxf(exQ.x, exQ.y), g1 = fmaxf(exQ.z, exQ.w); // bwd msg at seg end

    // ---- fused sweep: per chunk, bwd msgs from SS[g] (3-step local chain),
    //      forward f carried serially, beliefs written once ----
    const int xr = t & 7;
#pragma unroll
    for (int gg = 0; gg < 8; gg++) {
        // b at chunk end (position 4gg+3) directly from suffix product
        float bb0[4], bb1[4];
        bb0[3] = fmaxf(SS[gg].x * g0, SS[gg].y * g1);
        bb1[3] = fmaxf(SS[gg].z * g0, SS[gg].w * g1);
#pragma unroll
        for (int u = 2; u >= 0; u--) {
            int   i  = gg * 4 + u;
            int   o  = (bits >> (i + 1)) & 1;
            float p0 = o ? pt.pB0 : pt.pA0;
            float p1 = o ? pt.pB1 : pt.pA1;
            float y0 = p0 * bb0[u + 1];
            float y1 = p1 * bb1[u + 1];
            bb0[u] = fmaxf(y0 * pt.pd, y1 * pt.po);
            bb1[u] = fmaxf(y0 * pt.po, y1 * pt.pd);
        }
        float v0[4], v1[4];
#pragma unroll
        for (int u = 0; u < 4; u++) {
            int   i  = gg * 4 + u;
            int   o  = (bits >> i) & 1;
            float p0 = o ? pt.pB0 : pt.pA0;
            float p1 = o ? pt.pB1 : pt.pA1;
            float x0 = p0 * f0, x1 = p1 * f1;
            v0[u] = x0 * bb0[u];
            v1[u] = x1 * bb1[u];
            f0 = fmaxf(x0 * pt.pd, x1 * pt.po);
            f1 = fmaxf(x0 * pt.po, x1 * pt.pd);
        }
        sm4[(t * 8 + gg) ^ xr]        = make_float4(v0[0], v0[1], v0[2], v0[3]);
        sm4[(1024 + t * 8 + gg) ^ xr] = make_float4(v1[0], v1[1], v1[2], v1[3]);
    }
    __syncthreads();

    // ---- single LDS pass + fully-coalesced store: out[b][k][t] ----
    float4* out4 = reinterpret_cast<float4*>(out) + (size_t)b * 2048;
#pragma unroll
    for (int r = 0; r < 16; r++) {
        int w4 = r * 128 + t;
        int x  = (w4 >> 3) & 7;
        out4[w4] = sm4[w4 ^ x];
    }
}

// ---------------------------------------------------------------------------
extern "C" void kernel_launch(void* const* d_in, const int* in_sizes, int n_in,
                              void* d_out, int out_size)
{
    const float* jp  = nullptr;
    const float* bp  = nullptr;
    const int*   obs = nullptr;
    for (int i = 0; i < n_in; i++) {
        if (in_sizes[i] == 1)      jp  = (const float*)d_in[i];
        else if (in_sizes[i] == 2) bp  = (const float*)d_in[i];
        else                       obs = (const int*)d_in[i];
    }
    float* out = (float*)d_out;

    fused<<<BATCH, 128>>>(jp, bp, obs, out);
}